// round 4
// baseline (speedup 1.0000x reference)
#include <cuda_runtime.h>
#include <cuda_bf16.h>
#include <math.h>

// ---------------- problem constants ----------------
#define FH 200
#define FW 200
#define NPIX (FH*FW)          // 40000
#define ICH 256
#define OCH 256
#define NA 9
#define NSCORE (NPIX*NA)      // 360000
#define PRENMS 2000
#define RPN_TOPK 1000
#define NMS_TH 0.7f
#define MIN_SIZE 16.0f
#define IMGSZ 1600.0f
#define BBOX_CLIP 4.135166556742356f   // log(1000/16)

// ---------------- device scratch (static, no allocs) ----------------
__device__ __align__(16) float g_wT[2304 * 256];            // weights transposed [ic*9+k][oc]
__device__ __align__(16) float g_x[(size_t)OCH * NPIX];     // conv output, 41MB
__device__ __align__(16) float g_scores[NSCORE];            // sigmoid scores
__device__ __align__(16) float g_deltas[(size_t)NSCORE * 4];
__device__ unsigned int  g_hist[256];
__device__ unsigned int  g_sel_prefix;
__device__ unsigned int  g_sel_krem;
__device__ unsigned int  g_cand_count;
__device__ unsigned long long g_cand[4096];
__device__ int   g_topIdx[2048];
__device__ float g_topScore[2048];
__device__ __align__(16) float4 g_tmpB[2048];
__device__ float g_tmpS[2048];
__device__ __align__(16) float4 g_B[2048];
__device__ float g_SC[2048];
__device__ int   g_nvalid;
__device__ unsigned long long g_mask[PRENMS * 32];

// ---------------- kernel 0: init state ----------------
__global__ void k_init() {
    int t = threadIdx.x;
    if (t < 256) g_hist[t] = 0u;
    if (t == 0) { g_sel_prefix = 0u; g_sel_krem = PRENMS; g_cand_count = 0u; }
}

// ---------------- kernel 1: transpose conv weights ----------------
// conv_w: [oc][ic][3][3] -> g_wT[(ic*9+k)*256 + oc]
__global__ void k_transw(const float* __restrict__ cw) {
    int idx = blockIdx.x * blockDim.x + threadIdx.x;   // grid covers 2304*256 exactly
    int oc = idx & 255;
    int ick = idx >> 8;   // 0..2303
    g_wT[idx] = cw[oc * 2304 + ick];
}

// ---------------- kernel 2: 3x3 conv + bias + relu ----------------
// block: 256 threads, tile = 64 oc x 8x8 pixels, grid (25,25,4)
#define KC 8
__global__ __launch_bounds__(256) void k_conv(const float* __restrict__ feat,
                                              const float* __restrict__ bias) {
    __shared__ __align__(16) float sF[KC][10][12];
    __shared__ __align__(16) float sW[KC][9][64];

    const int t = threadIdx.x;
    const int gx0 = blockIdx.x * 8, gy0 = blockIdx.y * 8, oc0 = blockIdx.z * 64;
    const int ocg = t >> 4;                 // 0..15 -> 4 consecutive oc
    const int pxg = t & 15;                 // 0..15 -> 4 consecutive px in a row
    const int mrow = pxg >> 1;
    const int mcol = (pxg & 1) * 4;

    float acc[4][4] = {};

    for (int c0 = 0; c0 < ICH; c0 += KC) {
        // load feat tile (with halo, zero-pad OOB): KC*10*10 = 800
        for (int idx = t; idx < KC * 100; idx += 256) {
            int ic = idx / 100, rem = idx % 100;
            int r = rem / 10, c = rem % 10;
            int gy = gy0 + r - 1, gx = gx0 + c - 1;
            float v = 0.f;
            if ((unsigned)gy < FH && (unsigned)gx < FW)
                v = feat[((size_t)(c0 + ic) * FH + gy) * FW + gx];
            sF[ic][r][c] = v;
        }
        // load weights: KC*9*64 = 4608, coalesced in oc
        for (int idx = t; idx < KC * 9 * 64; idx += 256) {
            int oc = idx & 63;
            int kk = (idx >> 6) % 9;
            int ic = idx / 576;
            sW[ic][kk][oc] = g_wT[((size_t)(c0 + ic) * 9 + kk) * 256 + oc0 + oc];
        }
        __syncthreads();

        #pragma unroll 2
        for (int ic = 0; ic < KC; ++ic) {
            #pragma unroll
            for (int ky = 0; ky < 3; ++ky) {
                float f[6];
                const float* fr = &sF[ic][mrow + ky][mcol];
                #pragma unroll
                for (int q = 0; q < 6; ++q) f[q] = fr[q];
                #pragma unroll
                for (int kx = 0; kx < 3; ++kx) {
                    const float4 w = *reinterpret_cast<const float4*>(&sW[ic][ky * 3 + kx][ocg * 4]);
                    #pragma unroll
                    for (int j = 0; j < 4; ++j) {
                        float fv = f[kx + j];
                        acc[0][j] += w.x * fv;
                        acc[1][j] += w.y * fv;
                        acc[2][j] += w.z * fv;
                        acc[3][j] += w.w * fv;
                    }
                }
            }
        }
        __syncthreads();
    }

    const int gy = gy0 + mrow, gxb = gx0 + mcol;
    #pragma unroll
    for (int o = 0; o < 4; ++o) {
        int oc = oc0 + ocg * 4 + o;
        float b = bias[oc];
        float4 r;
        r.x = fmaxf(acc[o][0] + b, 0.f);
        r.y = fmaxf(acc[o][1] + b, 0.f);
        r.z = fmaxf(acc[o][2] + b, 0.f);
        r.w = fmaxf(acc[o][3] + b, 0.f);
        *reinterpret_cast<float4*>(&g_x[(size_t)oc * NPIX + gy * FW + gxb]) = r;
    }
}

// ---------------- kernel 3: 1x1 heads -> scores (sigmoid) + deltas ----------------
__global__ __launch_bounds__(256) void k_head(const float* __restrict__ cls_w,
                                              const float* __restrict__ cls_b,
                                              const float* __restrict__ reg_w,
                                              const float* __restrict__ reg_b) {
    __shared__ __align__(16) float sWt[128][48];   // 24KB, two 128-ic chunks
    const int t = threadIdx.x;
    const int p = blockIdx.x * 256 + t;
    const bool ok = (p < NPIX);

    float acc[48];
    #pragma unroll
    for (int c = 0; c < 48; ++c) acc[c] = 0.f;

    for (int cc = 0; cc < ICH; cc += 128) {
        for (int idx = t; idx < 128 * 48; idx += 256) {
            int ic = idx / 48, c = idx % 48;
            float w = 0.f;
            if (c < 9)        w = cls_w[c * 256 + cc + ic];
            else if (c < 45)  w = reg_w[(c - 9) * 256 + cc + ic];
            sWt[ic][c] = w;
        }
        __syncthreads();
        for (int ic = 0; ic < 128; ++ic) {
            float v = ok ? g_x[(size_t)(cc + ic) * NPIX + p] : 0.f;
            const float4* w4 = reinterpret_cast<const float4*>(sWt[ic]);
            #pragma unroll
            for (int q = 0; q < 12; ++q) {
                float4 w = w4[q];
                acc[4 * q + 0] += w.x * v;
                acc[4 * q + 1] += w.y * v;
                acc[4 * q + 2] += w.z * v;
                acc[4 * q + 3] += w.w * v;
            }
        }
        __syncthreads();
    }

    if (ok) {
        #pragma unroll
        for (int a = 0; a < 9; ++a) {
            float s = acc[a] + cls_b[a];
            g_scores[(size_t)p * 9 + a] = 1.f / (1.f + expf(-s));
        }
        #pragma unroll
        for (int c = 0; c < 36; ++c)
            g_deltas[(size_t)p * 36 + c] = acc[9 + c] + reg_b[c];
    }
}

// ---------------- kernels 4/5: radix-select (3 x 8-bit passes) ----------------
__global__ void k_hist(int pass) {
    __shared__ unsigned int sh[256];
    for (int b = threadIdx.x; b < 256; b += blockDim.x) sh[b] = 0u;
    __syncthreads();
    const unsigned pfx = g_sel_prefix;
    const int shift = 24 - 8 * pass;
    const int stride = gridDim.x * blockDim.x;
    for (int i = blockIdx.x * blockDim.x + threadIdx.x; i < NSCORE; i += stride) {
        unsigned key = __float_as_uint(g_scores[i]);
        bool ok = (pass == 0) || ((key >> (shift + 8)) == pfx);
        if (ok) atomicAdd(&sh[(key >> shift) & 255], 1u);
    }
    __syncthreads();
    for (int b = threadIdx.x; b < 256; b += blockDim.x)
        if (sh[b]) atomicAdd(&g_hist[b], sh[b]);
}

__global__ void k_select() {
    if (threadIdx.x == 0) {
        unsigned kRem = g_sel_krem, pfx = g_sel_prefix;
        unsigned cum = 0; int bestb = 0;
        for (int b = 255; b >= 0; --b) {
            unsigned c = g_hist[b];
            if (cum + c >= kRem) { bestb = b; break; }
            cum += c;
        }
        g_sel_prefix = (pfx << 8) | (unsigned)bestb;
        g_sel_krem = kRem - cum;
    }
    __syncthreads();
    for (int b = threadIdx.x; b < 256; b += blockDim.x) g_hist[b] = 0u;
}

// ---------------- kernel 6: compact candidates >= 24-bit threshold ----------------
__global__ void k_compact() {
    const unsigned p24 = g_sel_prefix;
    const int stride = gridDim.x * blockDim.x;
    for (int i = blockIdx.x * blockDim.x + threadIdx.x; i < NSCORE; i += stride) {
        unsigned key = __float_as_uint(g_scores[i]);
        if ((key >> 8) >= p24) {
            unsigned pos = atomicAdd(&g_cand_count, 1u);
            if (pos < 4096)
                g_cand[pos] = (((unsigned long long)(~key)) << 32) | (unsigned)i;
        }
    }
}

// ---------------- kernel 7: bitonic sort 4096 (1 block) -> top 2000 ----------------
__global__ __launch_bounds__(1024) void k_sort() {
    __shared__ unsigned long long s[4096];
    const int t = threadIdx.x;
    unsigned cnt = g_cand_count;
    if (cnt > 4096u) cnt = 4096u;
    for (int i = t; i < 4096; i += 1024)
        s[i] = (i < (int)cnt) ? g_cand[i] : 0xFFFFFFFFFFFFFFFFULL;
    __syncthreads();
    for (int k = 2; k <= 4096; k <<= 1) {
        for (int j = k >> 1; j > 0; j >>= 1) {
            for (int i = t; i < 4096; i += 1024) {
                int l = i ^ j;
                if (l > i) {
                    bool up = ((i & k) == 0);
                    unsigned long long a = s[i], b = s[l];
                    if ((a > b) == up) { s[i] = b; s[l] = a; }
                }
            }
            __syncthreads();
        }
    }
    for (int i = t; i < PRENMS; i += 1024) {
        int idx = (int)(s[i] & 0xFFFFFFFFULL);
        g_topIdx[i] = idx;
        g_topScore[i] = g_scores[idx];
    }
}

// ---------------- kernel 8: decode proposals + clip + stable valid-partition ----------------
__global__ __launch_bounds__(1024) void k_prop() {
    __shared__ int sFlag[2048], sA[2048], sB[2048];
    const int t = threadIdx.x;
    for (int i = t; i < 2048; i += 1024) sFlag[i] = 0;

    for (int i = t; i < PRENMS; i += 1024) {
        int idx = g_topIdx[i];
        int a = idx % 9, p = idx / 9;
        int px = p % FW, py = p / FW;
        int ai = a / 3, si = a % 3;
        float ar = (ai == 0) ? 0.5f : ((ai == 1) ? 1.0f : 2.0f);
        float scl = (si == 0) ? 128.f : ((si == 1) ? 256.f : 512.f);
        float hr = sqrtf(ar), wr = 1.0f / hr;
        float ws = wr * scl, hs = hr * scl;
        float bx = rintf(ws * 0.5f);   // numpy round (half-even) via rintf
        float by = rintf(hs * 0.5f);
        float sx = (float)(px * 8), sy = (float)(py * 8);
        float ax0 = sx - bx, ay0 = sy - by, ax1 = sx + bx, ay1 = sy + by;

        float dx = g_deltas[(size_t)idx * 4 + 0];
        float dy = g_deltas[(size_t)idx * 4 + 1];
        float dw = fminf(g_deltas[(size_t)idx * 4 + 2], BBOX_CLIP);
        float dh = fminf(g_deltas[(size_t)idx * 4 + 3], BBOX_CLIP);

        float w = ax1 - ax0, h = ay1 - ay0;
        float cx = ax0 + 0.5f * w, cy = ay0 + 0.5f * h;
        float pcx = dx * w + cx, pcy = dy * h + cy;
        float pw = expf(dw) * w, ph = expf(dh) * h;
        float x0 = pcx - 0.5f * pw, y0 = pcy - 0.5f * ph;
        float x1 = pcx + 0.5f * pw, y1 = pcy + 0.5f * ph;
        x0 = fminf(fmaxf(x0, 0.f), IMGSZ);
        y0 = fminf(fmaxf(y0, 0.f), IMGSZ);
        x1 = fminf(fmaxf(x1, 0.f), IMGSZ);
        y1 = fminf(fmaxf(y1, 0.f), IMGSZ);
        bool valid = ((x1 - x0) >= MIN_SIZE) && ((y1 - y0) >= MIN_SIZE);

        g_tmpB[i] = make_float4(x0, y0, x1, y1);
        g_tmpS[i] = valid ? g_topScore[i] : -1.0f;
        sFlag[i] = valid ? 1 : 0;
    }
    __syncthreads();

    // inclusive scan over 2048
    int* src = sA; int* dst = sB;
    for (int e = t; e < 2048; e += 1024) sA[e] = sFlag[e];
    __syncthreads();
    for (int off = 1; off < 2048; off <<= 1) {
        for (int e = t; e < 2048; e += 1024)
            dst[e] = src[e] + ((e >= off) ? src[e - off] : 0);
        __syncthreads();
        int* tmp = src; src = dst; dst = tmp;
    }
    const int nvalid = src[2047];
    if (t == 0) g_nvalid = nvalid;
    for (int i = t; i < PRENMS; i += 1024) {
        int f = sFlag[i];
        int rank = src[i] - f;          // exclusive rank among valid
        int pos = f ? rank : (nvalid + (i - rank));   // stable partition
        g_B[pos] = g_tmpB[i];
        g_SC[pos] = g_tmpS[i];
    }
}

// ---------------- kernel 9: NMS suppression masks ----------------
__global__ __launch_bounds__(64) void k_nms() {
    const int cb = blockIdx.x, rb = blockIdx.y;
    __shared__ float4 cbx[64];
    const int t = threadIdx.x;
    const int j0 = cb * 64;
    if (j0 + t < PRENMS) cbx[t] = g_B[j0 + t];
    __syncthreads();
    const int i = rb * 64 + t;
    if (i >= PRENMS) return;
    const float4 bi = g_B[i];
    const float areai = (bi.z - bi.x) * (bi.w - bi.y);
    unsigned long long m = 0ULL;
    const int jmax = min(64, PRENMS - j0);
    for (int jj = 0; jj < jmax; ++jj) {
        int j = j0 + jj;
        if (j <= i) continue;
        float4 bj = cbx[jj];
        float xx1 = fmaxf(bi.x, bj.x), yy1 = fmaxf(bi.y, bj.y);
        float xx2 = fminf(bi.z, bj.z), yy2 = fminf(bi.w, bj.w);
        float ww = fmaxf(xx2 - xx1, 0.f), hh = fmaxf(yy2 - yy1, 0.f);
        float inter = ww * hh;
        float areaj = (bj.z - bj.x) * (bj.w - bj.y);
        float iou = inter / (areai + areaj - inter + 1e-9f);
        if (iou > NMS_TH) m |= (1ULL << jj);
    }
    g_mask[(size_t)i * 32 + cb] = m;
}

// ---------------- kernel 10: sequential NMS scan + compact output ----------------
__global__ __launch_bounds__(1024) void k_final(float* __restrict__ out, int out_size) {
    const int t = threadIdx.x;
    for (int i = t; i < out_size; i += 1024) out[i] = 0.f;
    __shared__ unsigned char keepS[2048];
    __shared__ int sA[2048], sB[2048];
    for (int i = t; i < 2048; i += 1024) keepS[i] = 0;
    __syncthreads();

    if (t < 32) {
        const int PF = 8;
        unsigned long long rem = 0ULL;
        unsigned long long buf[PF];
        #pragma unroll
        for (int k = 0; k < PF; ++k) buf[k] = g_mask[(size_t)k * 32 + t];
        const int nv = g_nvalid;
        for (int i = 0; i < PRENMS; ++i) {
            unsigned long long w = __shfl_sync(0xffffffffu, rem, i >> 6);
            bool kept = (i < nv) && !((w >> (i & 63)) & 1ULL);
            unsigned long long row = buf[i & (PF - 1)];
            if (i + PF < PRENMS) buf[i & (PF - 1)] = g_mask[(size_t)(i + PF) * 32 + t];
            if (kept) rem |= row;
            if (t == 0) keepS[i] = kept ? 1 : 0;
        }
    }
    __syncthreads();

    int* src = sA; int* dst = sB;
    for (int e = t; e < 2048; e += 1024) sA[e] = keepS[e];
    __syncthreads();
    for (int off = 1; off < 2048; off <<= 1) {
        for (int e = t; e < 2048; e += 1024)
            dst[e] = src[e] + ((e >= off) ? src[e - off] : 0);
        __syncthreads();
        int* tmp = src; src = dst; dst = tmp;
    }
    for (int i = t; i < PRENMS; i += 1024) {
        if (keepS[i]) {
            int rank = src[i] - 1;
            if (rank < RPN_TOPK) {
                float4 b = g_B[i];
                out[rank * 4 + 0] = b.x;
                out[rank * 4 + 1] = b.y;
                out[rank * 4 + 2] = b.z;
                out[rank * 4 + 3] = b.w;
                out[out_size - RPN_TOPK + rank] = g_SC[i];
            }
        }
    }
}

// ---------------- launch ----------------
extern "C" void kernel_launch(void* const* d_in, const int* in_sizes, int n_in,
                              void* d_out, int out_size) {
    const float* feat   = (const float*)d_in[1];
    const float* conv_w = (const float*)d_in[2];
    const float* conv_b = (const float*)d_in[3];
    const float* cls_w  = (const float*)d_in[4];
    const float* cls_b  = (const float*)d_in[5];
    const float* reg_w  = (const float*)d_in[6];
    const float* reg_b  = (const float*)d_in[7];
    float* out = (float*)d_out;

    k_init<<<1, 256>>>();
    k_transw<<<2304, 256>>>(conv_w);
    k_conv<<<dim3(25, 25, 4), 256>>>(feat, conv_b);
    k_head<<<(NPIX + 255) / 256, 256>>>(cls_w, cls_b, reg_w, reg_b);
    for (int pass = 0; pass < 3; ++pass) {
        k_hist<<<512, 256>>>(pass);
        k_select<<<1, 256>>>();
    }
    k_compact<<<512, 256>>>();
    k_sort<<<1, 1024>>>();
    k_prop<<<1, 1024>>>();
    k_nms<<<dim3(32, 32), 64>>>();
    k_final<<<1, 1024>>>(out, out_size);
}

// round 5
// speedup vs baseline: 1.0751x; 1.0751x over previous
#include <cuda_runtime.h>
#include <cuda_bf16.h>
#include <math.h>

// ---------------- problem constants ----------------
#define FH 200
#define FW 200
#define NPIX (FH*FW)          // 40000
#define ICH 256
#define OCH 256
#define NA 9
#define NSCORE (NPIX*NA)      // 360000
#define PRENMS 2000
#define RPN_TOPK 1000
#define NMS_TH 0.7f
#define MIN_SIZE 16.0f
#define IMGSZ 1600.0f
#define BBOX_CLIP 4.135166556742356f   // log(1000/16)

// ---------------- f32x2 helpers (sm_100+ packed fp32 pipe) ----------------
__device__ __forceinline__ unsigned long long pk2(float x, float y) {
    unsigned long long r;
    asm("mov.b64 %0, {%1, %2};" : "=l"(r) : "f"(x), "f"(y));
    return r;
}
__device__ __forceinline__ void upk2(unsigned long long p, float& x, float& y) {
    asm("mov.b64 {%0, %1}, %2;" : "=f"(x), "=f"(y) : "l"(p));
}
__device__ __forceinline__ unsigned long long ffma2(unsigned long long a,
                                                    unsigned long long b,
                                                    unsigned long long c) {
    unsigned long long d;
    asm("fma.rn.f32x2 %0, %1, %2, %3;" : "=l"(d) : "l"(a), "l"(b), "l"(c));
    return d;
}

// ---------------- device scratch (static, no allocs) ----------------
__device__ __align__(16) float g_wT[2304 * 256];            // weights transposed [ic*9+k][oc]
__device__ __align__(16) float g_x[(size_t)OCH * NPIX];     // conv output, 41MB
__device__ __align__(16) float g_scores[NSCORE];            // sigmoid scores
__device__ __align__(16) float g_deltas[(size_t)NSCORE * 4];
__device__ unsigned int  g_hist[256];
__device__ unsigned int  g_sel_prefix;
__device__ unsigned int  g_sel_krem;
__device__ unsigned int  g_cand_count;
__device__ unsigned long long g_cand[4096];
__device__ int   g_topIdx[2048];
__device__ float g_topScore[2048];
__device__ __align__(16) float4 g_tmpB[2048];
__device__ float g_tmpS[2048];
__device__ __align__(16) float4 g_B[2048];
__device__ float g_SC[2048];
__device__ int   g_nvalid;
__device__ unsigned long long g_mask[PRENMS * 32];

// ---------------- kernel 0: init state ----------------
__global__ void k_init() {
    int t = threadIdx.x;
    if (t < 256) g_hist[t] = 0u;
    if (t == 0) { g_sel_prefix = 0u; g_sel_krem = PRENMS; g_cand_count = 0u; }
}

// ---------------- kernel 1: transpose conv weights ----------------
// conv_w: [oc][ic][3][3] -> g_wT[(ic*9+k)*256 + oc]
__global__ void k_transw(const float* __restrict__ cw) {
    int idx = blockIdx.x * blockDim.x + threadIdx.x;   // grid covers 2304*256 exactly
    int oc = idx & 255;
    int ick = idx >> 8;   // 0..2303
    g_wT[idx] = cw[oc * 2304 + ick];
}

// ---------------- kernel 2: 3x3 conv + bias + relu (f32x2) ----------------
// block: 256 threads, tile = 128 oc x 8x8 pixels, grid (25,25,2)
// each thread: 8 oc (4 f32x2 pairs) x 4 px
#define KC 8
__global__ __launch_bounds__(256) void k_conv(const float* __restrict__ feat,
                                              const float* __restrict__ bias) {
    __shared__ __align__(16) float sF[KC][10][12];
    __shared__ __align__(16) float sW[KC][9][128];

    const int t = threadIdx.x;
    const int gx0 = blockIdx.x * 8, gy0 = blockIdx.y * 8, oc0 = blockIdx.z * 128;
    const int ocg = t >> 4;                 // 0..15 -> 8 consecutive oc
    const int pxg = t & 15;                 // 0..15 -> 4 consecutive px in a row
    const int mrow = pxg >> 1;
    const int mcol = (pxg & 1) * 4;

    unsigned long long acc[4][4];           // [oc-pair][px]
    #pragma unroll
    for (int a = 0; a < 4; ++a)
        #pragma unroll
        for (int b = 0; b < 4; ++b) acc[a][b] = 0ull;

    for (int c0 = 0; c0 < ICH; c0 += KC) {
        // load feat tile (with halo, zero-pad OOB): KC*10*10 = 800
        for (int idx = t; idx < KC * 100; idx += 256) {
            int ic = idx / 100, rem = idx % 100;
            int r = rem / 10, c = rem % 10;
            int gy = gy0 + r - 1, gx = gx0 + c - 1;
            float v = 0.f;
            if ((unsigned)gy < FH && (unsigned)gx < FW)
                v = feat[((size_t)(c0 + ic) * FH + gy) * FW + gx];
            sF[ic][r][c] = v;
        }
        // load weights: KC*9*128 = 9216, coalesced in oc
        for (int idx = t; idx < KC * 9 * 128; idx += 256) {
            int oc = idx & 127;
            int kk = (idx >> 7) % 9;
            int ic = idx / 1152;
            sW[ic][kk][oc] = g_wT[((size_t)(c0 + ic) * 9 + kk) * 256 + oc0 + oc];
        }
        __syncthreads();

        #pragma unroll 2
        for (int ic = 0; ic < KC; ++ic) {
            #pragma unroll
            for (int ky = 0; ky < 3; ++ky) {
                unsigned long long f2[6];
                const float* fr = &sF[ic][mrow + ky][mcol];
                #pragma unroll
                for (int q = 0; q < 6; ++q) { float fv = fr[q]; f2[q] = pk2(fv, fv); }
                #pragma unroll
                for (int kx = 0; kx < 3; ++kx) {
                    const unsigned long long* wp =
                        reinterpret_cast<const unsigned long long*>(&sW[ic][ky * 3 + kx][ocg * 8]);
                    unsigned long long w0 = wp[0], w1 = wp[1], w2 = wp[2], w3 = wp[3];
                    #pragma unroll
                    for (int j = 0; j < 4; ++j) {
                        unsigned long long fv = f2[kx + j];
                        acc[0][j] = ffma2(w0, fv, acc[0][j]);
                        acc[1][j] = ffma2(w1, fv, acc[1][j]);
                        acc[2][j] = ffma2(w2, fv, acc[2][j]);
                        acc[3][j] = ffma2(w3, fv, acc[3][j]);
                    }
                }
            }
        }
        __syncthreads();
    }

    const int gy = gy0 + mrow, gxb = gx0 + mcol;
    #pragma unroll
    for (int op = 0; op < 4; ++op) {
        int oce = oc0 + ocg * 8 + op * 2;
        float be = bias[oce], bo = bias[oce + 1];
        float e0, o0, e1, o1, e2, o2, e3, o3;
        upk2(acc[op][0], e0, o0);
        upk2(acc[op][1], e1, o1);
        upk2(acc[op][2], e2, o2);
        upk2(acc[op][3], e3, o3);
        float4 re, ro;
        re.x = fmaxf(e0 + be, 0.f); re.y = fmaxf(e1 + be, 0.f);
        re.z = fmaxf(e2 + be, 0.f); re.w = fmaxf(e3 + be, 0.f);
        ro.x = fmaxf(o0 + bo, 0.f); ro.y = fmaxf(o1 + bo, 0.f);
        ro.z = fmaxf(o2 + bo, 0.f); ro.w = fmaxf(o3 + bo, 0.f);
        *reinterpret_cast<float4*>(&g_x[(size_t)oce * NPIX + gy * FW + gxb]) = re;
        *reinterpret_cast<float4*>(&g_x[(size_t)(oce + 1) * NPIX + gy * FW + gxb]) = ro;
    }
}

// ---------------- kernel 3: 1x1 heads (f32x2, MLP=8) ----------------
__global__ __launch_bounds__(256) void k_head(const float* __restrict__ cls_w,
                                              const float* __restrict__ cls_b,
                                              const float* __restrict__ reg_w,
                                              const float* __restrict__ reg_b) {
    __shared__ __align__(16) float sWt[128][48];   // 24KB, two 128-ic chunks
    const int t = threadIdx.x;
    const int p = blockIdx.x * 256 + t;
    const bool ok = (p < NPIX);

    unsigned long long acc2[24];
    #pragma unroll
    for (int c = 0; c < 24; ++c) acc2[c] = 0ull;

    for (int cc = 0; cc < ICH; cc += 128) {
        for (int idx = t; idx < 128 * 48; idx += 256) {
            int ic = idx / 48, c = idx % 48;
            float w = 0.f;
            if (c < 9)        w = cls_w[c * 256 + cc + ic];
            else if (c < 45)  w = reg_w[(c - 9) * 256 + cc + ic];
            sWt[ic][c] = w;
        }
        __syncthreads();
        #pragma unroll 2
        for (int icb = 0; icb < 128; icb += 8) {
            float v[8];
            #pragma unroll
            for (int u = 0; u < 8; ++u)
                v[u] = ok ? g_x[(size_t)(cc + icb + u) * NPIX + p] : 0.f;
            #pragma unroll
            for (int u = 0; u < 8; ++u) {
                unsigned long long v2 = pk2(v[u], v[u]);
                const ulonglong2* w2 = reinterpret_cast<const ulonglong2*>(sWt[icb + u]);
                #pragma unroll
                for (int q = 0; q < 12; ++q) {
                    ulonglong2 wv = w2[q];
                    acc2[2 * q + 0] = ffma2(wv.x, v2, acc2[2 * q + 0]);
                    acc2[2 * q + 1] = ffma2(wv.y, v2, acc2[2 * q + 1]);
                }
            }
        }
        __syncthreads();
    }

    if (ok) {
        float acc[48];
        #pragma unroll
        for (int q = 0; q < 24; ++q) upk2(acc2[q], acc[2 * q], acc[2 * q + 1]);
        #pragma unroll
        for (int a = 0; a < 9; ++a) {
            float s = acc[a] + cls_b[a];
            g_scores[(size_t)p * 9 + a] = 1.f / (1.f + expf(-s));
        }
        #pragma unroll
        for (int c = 0; c < 36; ++c)
            g_deltas[(size_t)p * 36 + c] = acc[9 + c] + reg_b[c];
    }
}

// ---------------- kernels 4/5: radix-select (3 x 8-bit passes) ----------------
__global__ void k_hist(int pass) {
    __shared__ unsigned int sh[256];
    for (int b = threadIdx.x; b < 256; b += blockDim.x) sh[b] = 0u;
    __syncthreads();
    const unsigned pfx = g_sel_prefix;
    const int shift = 24 - 8 * pass;
    const int stride = gridDim.x * blockDim.x;
    for (int i = blockIdx.x * blockDim.x + threadIdx.x; i < NSCORE; i += stride) {
        unsigned key = __float_as_uint(g_scores[i]);
        bool ok = (pass == 0) || ((key >> (shift + 8)) == pfx);
        if (ok) atomicAdd(&sh[(key >> shift) & 255], 1u);
    }
    __syncthreads();
    for (int b = threadIdx.x; b < 256; b += blockDim.x)
        if (sh[b]) atomicAdd(&g_hist[b], sh[b]);
}

__global__ void k_select() {
    if (threadIdx.x == 0) {
        unsigned kRem = g_sel_krem, pfx = g_sel_prefix;
        unsigned cum = 0; int bestb = 0;
        for (int b = 255; b >= 0; --b) {
            unsigned c = g_hist[b];
            if (cum + c >= kRem) { bestb = b; break; }
            cum += c;
        }
        g_sel_prefix = (pfx << 8) | (unsigned)bestb;
        g_sel_krem = kRem - cum;
    }
    __syncthreads();
    for (int b = threadIdx.x; b < 256; b += blockDim.x) g_hist[b] = 0u;
}

// ---------------- kernel 6: compact candidates >= 24-bit threshold ----------------
__global__ void k_compact() {
    const unsigned p24 = g_sel_prefix;
    const int stride = gridDim.x * blockDim.x;
    for (int i = blockIdx.x * blockDim.x + threadIdx.x; i < NSCORE; i += stride) {
        unsigned key = __float_as_uint(g_scores[i]);
        if ((key >> 8) >= p24) {
            unsigned pos = atomicAdd(&g_cand_count, 1u);
            if (pos < 4096)
                g_cand[pos] = (((unsigned long long)(~key)) << 32) | (unsigned)i;
        }
    }
}

// ---------------- kernel 7: bitonic sort 4096 (1 block) -> top 2000 ----------------
__global__ __launch_bounds__(1024) void k_sort() {
    __shared__ unsigned long long s[4096];
    const int t = threadIdx.x;
    unsigned cnt = g_cand_count;
    if (cnt > 4096u) cnt = 4096u;
    for (int i = t; i < 4096; i += 1024)
        s[i] = (i < (int)cnt) ? g_cand[i] : 0xFFFFFFFFFFFFFFFFULL;
    __syncthreads();
    for (int k = 2; k <= 4096; k <<= 1) {
        for (int j = k >> 1; j > 0; j >>= 1) {
            for (int i = t; i < 4096; i += 1024) {
                int l = i ^ j;
                if (l > i) {
                    bool up = ((i & k) == 0);
                    unsigned long long a = s[i], b = s[l];
                    if ((a > b) == up) { s[i] = b; s[l] = a; }
                }
            }
            __syncthreads();
        }
    }
    for (int i = t; i < PRENMS; i += 1024) {
        int idx = (int)(s[i] & 0xFFFFFFFFULL);
        g_topIdx[i] = idx;
        g_topScore[i] = g_scores[idx];
    }
}

// ---------------- kernel 8: decode proposals + clip + stable valid-partition ----------------
__global__ __launch_bounds__(1024) void k_prop() {
    __shared__ int sFlag[2048], sA[2048], sB[2048];
    const int t = threadIdx.x;
    for (int i = t; i < 2048; i += 1024) sFlag[i] = 0;

    for (int i = t; i < PRENMS; i += 1024) {
        int idx = g_topIdx[i];
        int a = idx % 9, p = idx / 9;
        int px = p % FW, py = p / FW;
        int ai = a / 3, si = a % 3;
        float ar = (ai == 0) ? 0.5f : ((ai == 1) ? 1.0f : 2.0f);
        float scl = (si == 0) ? 128.f : ((si == 1) ? 256.f : 512.f);
        float hr = sqrtf(ar), wr = 1.0f / hr;
        float ws = wr * scl, hs = hr * scl;
        float bx = rintf(ws * 0.5f);   // numpy round (half-even) via rintf
        float by = rintf(hs * 0.5f);
        float sx = (float)(px * 8), sy = (float)(py * 8);
        float ax0 = sx - bx, ay0 = sy - by, ax1 = sx + bx, ay1 = sy + by;

        float dx = g_deltas[(size_t)idx * 4 + 0];
        float dy = g_deltas[(size_t)idx * 4 + 1];
        float dw = fminf(g_deltas[(size_t)idx * 4 + 2], BBOX_CLIP);
        float dh = fminf(g_deltas[(size_t)idx * 4 + 3], BBOX_CLIP);

        float w = ax1 - ax0, h = ay1 - ay0;
        float cx = ax0 + 0.5f * w, cy = ay0 + 0.5f * h;
        float pcx = dx * w + cx, pcy = dy * h + cy;
        float pw = expf(dw) * w, ph = expf(dh) * h;
        float x0 = pcx - 0.5f * pw, y0 = pcy - 0.5f * ph;
        float x1 = pcx + 0.5f * pw, y1 = pcy + 0.5f * ph;
        x0 = fminf(fmaxf(x0, 0.f), IMGSZ);
        y0 = fminf(fmaxf(y0, 0.f), IMGSZ);
        x1 = fminf(fmaxf(x1, 0.f), IMGSZ);
        y1 = fminf(fmaxf(y1, 0.f), IMGSZ);
        bool valid = ((x1 - x0) >= MIN_SIZE) && ((y1 - y0) >= MIN_SIZE);

        g_tmpB[i] = make_float4(x0, y0, x1, y1);
        g_tmpS[i] = valid ? g_topScore[i] : -1.0f;
        sFlag[i] = valid ? 1 : 0;
    }
    __syncthreads();

    // inclusive scan over 2048
    int* src = sA; int* dst = sB;
    for (int e = t; e < 2048; e += 1024) sA[e] = sFlag[e];
    __syncthreads();
    for (int off = 1; off < 2048; off <<= 1) {
        for (int e = t; e < 2048; e += 1024)
            dst[e] = src[e] + ((e >= off) ? src[e - off] : 0);
        __syncthreads();
        int* tmp = src; src = dst; dst = tmp;
    }
    const int nvalid = src[2047];
    if (t == 0) g_nvalid = nvalid;
    for (int i = t; i < PRENMS; i += 1024) {
        int f = sFlag[i];
        int rank = src[i] - f;          // exclusive rank among valid
        int pos = f ? rank : (nvalid + (i - rank));   // stable partition
        g_B[pos] = g_tmpB[i];
        g_SC[pos] = g_tmpS[i];
    }
}

// ---------------- kernel 9: NMS suppression masks ----------------
__global__ __launch_bounds__(64) void k_nms() {
    const int cb = blockIdx.x, rb = blockIdx.y;
    __shared__ float4 cbx[64];
    const int t = threadIdx.x;
    const int j0 = cb * 64;
    if (j0 + t < PRENMS) cbx[t] = g_B[j0 + t];
    __syncthreads();
    const int i = rb * 64 + t;
    if (i >= PRENMS) return;
    const float4 bi = g_B[i];
    const float areai = (bi.z - bi.x) * (bi.w - bi.y);
    unsigned long long m = 0ULL;
    const int jmax = min(64, PRENMS - j0);
    for (int jj = 0; jj < jmax; ++jj) {
        int j = j0 + jj;
        if (j <= i) continue;
        float4 bj = cbx[jj];
        float xx1 = fmaxf(bi.x, bj.x), yy1 = fmaxf(bi.y, bj.y);
        float xx2 = fminf(bi.z, bj.z), yy2 = fminf(bi.w, bj.w);
        float ww = fmaxf(xx2 - xx1, 0.f), hh = fmaxf(yy2 - yy1, 0.f);
        float inter = ww * hh;
        float areaj = (bj.z - bj.x) * (bj.w - bj.y);
        float iou = inter / (areai + areaj - inter + 1e-9f);
        if (iou > NMS_TH) m |= (1ULL << jj);
    }
    g_mask[(size_t)i * 32 + cb] = m;
}

// ---------------- kernel 10: sequential NMS scan + compact output ----------------
__global__ __launch_bounds__(1024) void k_final(float* __restrict__ out, int out_size) {
    const int t = threadIdx.x;
    for (int i = t; i < out_size; i += 1024) out[i] = 0.f;
    __shared__ unsigned char keepS[2048];
    __shared__ int sA[2048], sB[2048];
    for (int i = t; i < 2048; i += 1024) keepS[i] = 0;
    __syncthreads();

    if (t < 32) {
        const int PF = 8;
        unsigned long long rem = 0ULL;
        unsigned long long buf[PF];
        #pragma unroll
        for (int k = 0; k < PF; ++k) buf[k] = g_mask[(size_t)k * 32 + t];
        const int nv = g_nvalid;
        for (int i = 0; i < PRENMS; ++i) {
            unsigned long long w = __shfl_sync(0xffffffffu, rem, i >> 6);
            bool kept = (i < nv) && !((w >> (i & 63)) & 1ULL);
            unsigned long long row = buf[i & (PF - 1)];
            if (i + PF < PRENMS) buf[i & (PF - 1)] = g_mask[(size_t)(i + PF) * 32 + t];
            if (kept) rem |= row;
            if (t == 0) keepS[i] = kept ? 1 : 0;
        }
    }
    __syncthreads();

    int* src = sA; int* dst = sB;
    for (int e = t; e < 2048; e += 1024) sA[e] = keepS[e];
    __syncthreads();
    for (int off = 1; off < 2048; off <<= 1) {
        for (int e = t; e < 2048; e += 1024)
            dst[e] = src[e] + ((e >= off) ? src[e - off] : 0);
        __syncthreads();
        int* tmp = src; src = dst; dst = tmp;
    }
    for (int i = t; i < PRENMS; i += 1024) {
        if (keepS[i]) {
            int rank = src[i] - 1;
            if (rank < RPN_TOPK) {
                float4 b = g_B[i];
                out[rank * 4 + 0] = b.x;
                out[rank * 4 + 1] = b.y;
                out[rank * 4 + 2] = b.z;
                out[rank * 4 + 3] = b.w;
                out[out_size - RPN_TOPK + rank] = g_SC[i];
            }
        }
    }
}

// ---------------- launch ----------------
extern "C" void kernel_launch(void* const* d_in, const int* in_sizes, int n_in,
                              void* d_out, int out_size) {
    const float* feat   = (const float*)d_in[1];
    const float* conv_w = (const float*)d_in[2];
    const float* conv_b = (const float*)d_in[3];
    const float* cls_w  = (const float*)d_in[4];
    const float* cls_b  = (const float*)d_in[5];
    const float* reg_w  = (const float*)d_in[6];
    const float* reg_b  = (const float*)d_in[7];
    float* out = (float*)d_out;

    k_init<<<1, 256>>>();
    k_transw<<<2304, 256>>>(conv_w);
    k_conv<<<dim3(25, 25, 2), 256>>>(feat, conv_b);
    k_head<<<(NPIX + 255) / 256, 256>>>(cls_w, cls_b, reg_w, reg_b);
    for (int pass = 0; pass < 3; ++pass) {
        k_hist<<<512, 256>>>(pass);
        k_select<<<1, 256>>>();
    }
    k_compact<<<512, 256>>>();
    k_sort<<<1, 1024>>>();
    k_prop<<<1, 1024>>>();
    k_nms<<<dim3(32, 32), 64>>>();
    k_final<<<1, 1024>>>(out, out_size);
}

// round 6
// speedup vs baseline: 1.4257x; 1.3260x over previous
#include <cuda_runtime.h>
#include <cuda_bf16.h>
#include <math.h>
#include <stdint.h>

// ---------------- problem constants ----------------
#define FH 200
#define FW 200
#define NPIX (FH*FW)          // 40000
#define ICH 256
#define OCH 256
#define NA 9
#define NSCORE (NPIX*NA)      // 360000
#define PRENMS 2000
#define RPN_TOPK 1000
#define NMS_TH 0.7f
#define MIN_SIZE 16.0f
#define IMGSZ 1600.0f
#define BBOX_CLIP 4.135166556742356f   // log(1000/16)

// ---------------- f32x2 helpers (sm_100+ packed fp32 pipe) ----------------
__device__ __forceinline__ unsigned long long pk2(float x, float y) {
    unsigned long long r;
    asm("mov.b64 %0, {%1, %2};" : "=l"(r) : "f"(x), "f"(y));
    return r;
}
__device__ __forceinline__ void upk2(unsigned long long p, float& x, float& y) {
    asm("mov.b64 {%0, %1}, %2;" : "=f"(x), "=f"(y) : "l"(p));
}
__device__ __forceinline__ unsigned long long ffma2(unsigned long long a,
                                                    unsigned long long b,
                                                    unsigned long long c) {
    unsigned long long d;
    asm("fma.rn.f32x2 %0, %1, %2, %3;" : "=l"(d) : "l"(a), "l"(b), "l"(c));
    return d;
}

// ---------------- cp.async helpers ----------------
__device__ __forceinline__ void cpa16(uint32_t dst, const void* src) {
    asm volatile("cp.async.cg.shared.global [%0], [%1], 16;" :: "r"(dst), "l"(src));
}
__device__ __forceinline__ void cpa4(uint32_t dst, const void* src, bool ok) {
    int sz = ok ? 4 : 0;
    asm volatile("cp.async.ca.shared.global [%0], [%1], 4, %2;" :: "r"(dst), "l"(src), "r"(sz));
}
__device__ __forceinline__ void cpa_commit() {
    asm volatile("cp.async.commit_group;" ::: "memory");
}
__device__ __forceinline__ void cpa_wait1() {
    asm volatile("cp.async.wait_group 1;" ::: "memory");
}
__device__ __forceinline__ void cpa_wait0() {
    asm volatile("cp.async.wait_group 0;" ::: "memory");
}

// ---------------- device scratch (static, no allocs) ----------------
__device__ __align__(16) float g_wT[2304 * 256];            // weights transposed [ic*9+k][oc]
__device__ __align__(16) float g_x[(size_t)OCH * NPIX];     // conv output, 41MB
__device__ __align__(16) float g_scores[NSCORE];            // sigmoid scores
__device__ __align__(16) float g_deltas[(size_t)NSCORE * 4];
__device__ unsigned int  g_hist[256];
__device__ unsigned int  g_sel_prefix;
__device__ unsigned int  g_sel_krem;
__device__ unsigned int  g_cand_count;
__device__ unsigned long long g_cand[4096];
__device__ int   g_topIdx[2048];
__device__ float g_topScore[2048];
__device__ __align__(16) float4 g_tmpB[2048];
__device__ float g_tmpS[2048];
__device__ __align__(16) float4 g_B[2048];
__device__ float g_SC[2048];
__device__ int   g_nvalid;
__device__ unsigned long long g_mask[PRENMS * 32];

// ---------------- kernel 0: init state ----------------
__global__ void k_init() {
    int t = threadIdx.x;
    if (t < 256) g_hist[t] = 0u;
    if (t == 0) { g_sel_prefix = 0u; g_sel_krem = PRENMS; g_cand_count = 0u; }
}

// ---------------- kernel 1: transpose conv weights ----------------
// conv_w: [oc][ic][3][3] -> g_wT[(ic*9+k)*256 + oc]
__global__ void k_transw(const float* __restrict__ cw) {
    int idx = blockIdx.x * blockDim.x + threadIdx.x;   // grid covers 2304*256 exactly
    int oc = idx & 255;
    int ick = idx >> 8;   // 0..2303
    g_wT[idx] = cw[oc * 2304 + ick];
}

// ---------------- kernel 2: 3x3 conv + bias + relu (f32x2, cp.async pipelined) ----------------
// block: 256 threads, tile = 128 oc x 8x8 pixels, grid (25,25,2)
// each thread: 8 oc (4 f32x2 pairs) x 4 px.  KC=4 ic per stage, double-buffered.
#define KC 4
#define STAGEF (KC*9*128 + KC*120)    // 4608 + 480 = 5088 floats per stage
__global__ __launch_bounds__(256) void k_conv(const float* __restrict__ feat,
                                              const float* __restrict__ bias) {
    __shared__ __align__(16) float sbuf[2][STAGEF];

    const int t = threadIdx.x;
    const int gx0 = blockIdx.x * 8, gy0 = blockIdx.y * 8, oc0 = blockIdx.z * 128;
    const int ocg = t >> 4;                 // 0..15 -> 8 consecutive oc
    const int pxg = t & 15;                 // 0..15 -> 4 consecutive px in a row
    const int mrow = pxg >> 1;
    const int mcol = (pxg & 1) * 4;

    const uint32_t smem0 = (uint32_t)__cvta_generic_to_shared(&sbuf[0][0]);

    unsigned long long acc[4][4];           // [oc-pair][px]
    #pragma unroll
    for (int a = 0; a < 4; ++a)
        #pragma unroll
        for (int b = 0; b < 4; ++b) acc[a][b] = 0ull;

    // --- stage issue: weights (1152 x 16B chunks) + feat (480 x 4B incl pad rows) ---
    auto issue_stage = [&](int c0, int s) {
        const uint32_t swd = smem0 + (uint32_t)(s * STAGEF) * 4u;
        const uint32_t sfd = swd + (uint32_t)(KC * 9 * 128) * 4u;
        const float* wbase = g_wT + (size_t)c0 * 9 * 256 + oc0;
        #pragma unroll
        for (int k = 0; k < 5; ++k) {
            int j = t + k * 256;
            if (j < KC * 9 * 32) {                 // 1152 chunks
                int row = j >> 5;                  // ic*9+kk, 0..35
                int col = (j & 31) * 4;
                cpa16(swd + (uint32_t)(row * 128 + col) * 4u,
                      wbase + (size_t)row * 256 + col);
            }
        }
        #pragma unroll
        for (int k = 0; k < 2; ++k) {
            int idx = t + k * 256;
            if (idx < KC * 100) {                  // 400 elems
                int ic = idx / 100, rem = idx % 100;
                int r = rem / 10, c = rem % 10;
                int gy = gy0 + r - 1, gx = gx0 + c - 1;
                bool ok = ((unsigned)gy < FH) && ((unsigned)gx < FW);
                const float* src = ok ? (feat + ((size_t)(c0 + ic) * FH + gy) * FW + gx)
                                      : feat;
                cpa4(sfd + (uint32_t)(ic * 120 + r * 12 + c) * 4u, src, ok);
            }
        }
        cpa_commit();
    };

    issue_stage(0, 0);

    const int NST = ICH / KC;   // 64
    for (int it = 0; it < NST; ++it) {
        if (it < NST - 1) { issue_stage((it + 1) * KC, (it + 1) & 1); cpa_wait1(); }
        else              { cpa_wait0(); }
        __syncthreads();

        const float* sWb = &sbuf[it & 1][0];
        const float* sFb = sWb + KC * 9 * 128;

        #pragma unroll
        for (int ic = 0; ic < KC; ++ic) {
            #pragma unroll
            for (int ky = 0; ky < 3; ++ky) {
                const float* fr = &sFb[ic * 120 + (mrow + ky) * 12 + mcol];
                float4 fa = *reinterpret_cast<const float4*>(fr);
                float2 fb = *reinterpret_cast<const float2*>(fr + 4);
                unsigned long long f2[6];
                f2[0] = pk2(fa.x, fa.x); f2[1] = pk2(fa.y, fa.y);
                f2[2] = pk2(fa.z, fa.z); f2[3] = pk2(fa.w, fa.w);
                f2[4] = pk2(fb.x, fb.x); f2[5] = pk2(fb.y, fb.y);
                #pragma unroll
                for (int kx = 0; kx < 3; ++kx) {
                    const unsigned long long* wp =
                        reinterpret_cast<const unsigned long long*>(
                            &sWb[ic * 1152 + (ky * 3 + kx) * 128 + ocg * 8]);
                    unsigned long long w0 = wp[0], w1 = wp[1], w2 = wp[2], w3 = wp[3];
                    #pragma unroll
                    for (int j = 0; j < 4; ++j) {
                        unsigned long long fv = f2[kx + j];
                        acc[0][j] = ffma2(w0, fv, acc[0][j]);
                        acc[1][j] = ffma2(w1, fv, acc[1][j]);
                        acc[2][j] = ffma2(w2, fv, acc[2][j]);
                        acc[3][j] = ffma2(w3, fv, acc[3][j]);
                    }
                }
            }
        }
        __syncthreads();
    }

    const int gy = gy0 + mrow, gxb = gx0 + mcol;
    #pragma unroll
    for (int op = 0; op < 4; ++op) {
        int oce = oc0 + ocg * 8 + op * 2;
        float be = bias[oce], bo = bias[oce + 1];
        float e0, o0, e1, o1, e2, o2, e3, o3;
        upk2(acc[op][0], e0, o0);
        upk2(acc[op][1], e1, o1);
        upk2(acc[op][2], e2, o2);
        upk2(acc[op][3], e3, o3);
        float4 re, ro;
        re.x = fmaxf(e0 + be, 0.f); re.y = fmaxf(e1 + be, 0.f);
        re.z = fmaxf(e2 + be, 0.f); re.w = fmaxf(e3 + be, 0.f);
        ro.x = fmaxf(o0 + bo, 0.f); ro.y = fmaxf(o1 + bo, 0.f);
        ro.z = fmaxf(o2 + bo, 0.f); ro.w = fmaxf(o3 + bo, 0.f);
        *reinterpret_cast<float4*>(&g_x[(size_t)oce * NPIX + gy * FW + gxb]) = re;
        *reinterpret_cast<float4*>(&g_x[(size_t)(oce + 1) * NPIX + gy * FW + gxb]) = ro;
    }
}

// ---------------- kernel 3: 1x1 heads (f32x2, MLP=8) ----------------
__global__ __launch_bounds__(256) void k_head(const float* __restrict__ cls_w,
                                              const float* __restrict__ cls_b,
                                              const float* __restrict__ reg_w,
                                              const float* __restrict__ reg_b) {
    __shared__ __align__(16) float sWt[128][48];   // 24KB, two 128-ic chunks
    const int t = threadIdx.x;
    const int p = blockIdx.x * 256 + t;
    const bool ok = (p < NPIX);

    unsigned long long acc2[24];
    #pragma unroll
    for (int c = 0; c < 24; ++c) acc2[c] = 0ull;

    for (int cc = 0; cc < ICH; cc += 128) {
        for (int idx = t; idx < 128 * 48; idx += 256) {
            int ic = idx / 48, c = idx % 48;
            float w = 0.f;
            if (c < 9)        w = cls_w[c * 256 + cc + ic];
            else if (c < 45)  w = reg_w[(c - 9) * 256 + cc + ic];
            sWt[ic][c] = w;
        }
        __syncthreads();
        #pragma unroll 2
        for (int icb = 0; icb < 128; icb += 8) {
            float v[8];
            #pragma unroll
            for (int u = 0; u < 8; ++u)
                v[u] = ok ? g_x[(size_t)(cc + icb + u) * NPIX + p] : 0.f;
            #pragma unroll
            for (int u = 0; u < 8; ++u) {
                unsigned long long v2 = pk2(v[u], v[u]);
                const ulonglong2* w2 = reinterpret_cast<const ulonglong2*>(sWt[icb + u]);
                #pragma unroll
                for (int q = 0; q < 12; ++q) {
                    ulonglong2 wv = w2[q];
                    acc2[2 * q + 0] = ffma2(wv.x, v2, acc2[2 * q + 0]);
                    acc2[2 * q + 1] = ffma2(wv.y, v2, acc2[2 * q + 1]);
                }
            }
        }
        __syncthreads();
    }

    if (ok) {
        float acc[48];
        #pragma unroll
        for (int q = 0; q < 24; ++q) upk2(acc2[q], acc[2 * q], acc[2 * q + 1]);
        #pragma unroll
        for (int a = 0; a < 9; ++a) {
            float s = acc[a] + cls_b[a];
            g_scores[(size_t)p * 9 + a] = 1.f / (1.f + expf(-s));
        }
        #pragma unroll
        for (int c = 0; c < 36; ++c)
            g_deltas[(size_t)p * 36 + c] = acc[9 + c] + reg_b[c];
    }
}

// ---------------- kernels 4/5: radix-select (3 x 8-bit passes) ----------------
__global__ void k_hist(int pass) {
    __shared__ unsigned int sh[256];
    for (int b = threadIdx.x; b < 256; b += blockDim.x) sh[b] = 0u;
    __syncthreads();
    const unsigned pfx = g_sel_prefix;
    const int shift = 24 - 8 * pass;
    const int stride = gridDim.x * blockDim.x;
    for (int i = blockIdx.x * blockDim.x + threadIdx.x; i < NSCORE; i += stride) {
        unsigned key = __float_as_uint(g_scores[i]);
        bool ok = (pass == 0) || ((key >> (shift + 8)) == pfx);
        if (ok) atomicAdd(&sh[(key >> shift) & 255], 1u);
    }
    __syncthreads();
    for (int b = threadIdx.x; b < 256; b += blockDim.x)
        if (sh[b]) atomicAdd(&g_hist[b], sh[b]);
}

__global__ void k_select() {
    if (threadIdx.x == 0) {
        unsigned kRem = g_sel_krem, pfx = g_sel_prefix;
        unsigned cum = 0; int bestb = 0;
        for (int b = 255; b >= 0; --b) {
            unsigned c = g_hist[b];
            if (cum + c >= kRem) { bestb = b; break; }
            cum += c;
        }
        g_sel_prefix = (pfx << 8) | (unsigned)bestb;
        g_sel_krem = kRem - cum;
    }
    __syncthreads();
    for (int b = threadIdx.x; b < 256; b += blockDim.x) g_hist[b] = 0u;
}

// ---------------- kernel 6: compact candidates >= 24-bit threshold ----------------
__global__ void k_compact() {
    const unsigned p24 = g_sel_prefix;
    const int stride = gridDim.x * blockDim.x;
    for (int i = blockIdx.x * blockDim.x + threadIdx.x; i < NSCORE; i += stride) {
        unsigned key = __float_as_uint(g_scores[i]);
        if ((key >> 8) >= p24) {
            unsigned pos = atomicAdd(&g_cand_count, 1u);
            if (pos < 4096)
                g_cand[pos] = (((unsigned long long)(~key)) << 32) | (unsigned)i;
        }
    }
}

// ---------------- kernel 7: bitonic sort 4096 (1 block) -> top 2000 ----------------
__global__ __launch_bounds__(1024) void k_sort() {
    __shared__ unsigned long long s[4096];
    const int t = threadIdx.x;
    unsigned cnt = g_cand_count;
    if (cnt > 4096u) cnt = 4096u;
    for (int i = t; i < 4096; i += 1024)
        s[i] = (i < (int)cnt) ? g_cand[i] : 0xFFFFFFFFFFFFFFFFULL;
    __syncthreads();
    for (int k = 2; k <= 4096; k <<= 1) {
        for (int j = k >> 1; j > 0; j >>= 1) {
            for (int i = t; i < 4096; i += 1024) {
                int l = i ^ j;
                if (l > i) {
                    bool up = ((i & k) == 0);
                    unsigned long long a = s[i], b = s[l];
                    if ((a > b) == up) { s[i] = b; s[l] = a; }
                }
            }
            __syncthreads();
        }
    }
    for (int i = t; i < PRENMS; i += 1024) {
        int idx = (int)(s[i] & 0xFFFFFFFFULL);
        g_topIdx[i] = idx;
        g_topScore[i] = g_scores[idx];
    }
}

// ---------------- kernel 8: decode proposals + clip + stable valid-partition ----------------
__global__ __launch_bounds__(1024) void k_prop() {
    __shared__ int sFlag[2048], sA[2048], sB[2048];
    const int t = threadIdx.x;
    for (int i = t; i < 2048; i += 1024) sFlag[i] = 0;

    for (int i = t; i < PRENMS; i += 1024) {
        int idx = g_topIdx[i];
        int a = idx % 9, p = idx / 9;
        int px = p % FW, py = p / FW;
        int ai = a / 3, si = a % 3;
        float ar = (ai == 0) ? 0.5f : ((ai == 1) ? 1.0f : 2.0f);
        float scl = (si == 0) ? 128.f : ((si == 1) ? 256.f : 512.f);
        float hr = sqrtf(ar), wr = 1.0f / hr;
        float ws = wr * scl, hs = hr * scl;
        float bx = rintf(ws * 0.5f);   // numpy round (half-even) via rintf
        float by = rintf(hs * 0.5f);
        float sx = (float)(px * 8), sy = (float)(py * 8);
        float ax0 = sx - bx, ay0 = sy - by, ax1 = sx + bx, ay1 = sy + by;

        float dx = g_deltas[(size_t)idx * 4 + 0];
        float dy = g_deltas[(size_t)idx * 4 + 1];
        float dw = fminf(g_deltas[(size_t)idx * 4 + 2], BBOX_CLIP);
        float dh = fminf(g_deltas[(size_t)idx * 4 + 3], BBOX_CLIP);

        float w = ax1 - ax0, h = ay1 - ay0;
        float cx = ax0 + 0.5f * w, cy = ay0 + 0.5f * h;
        float pcx = dx * w + cx, pcy = dy * h + cy;
        float pw = expf(dw) * w, ph = expf(dh) * h;
        float x0 = pcx - 0.5f * pw, y0 = pcy - 0.5f * ph;
        float x1 = pcx + 0.5f * pw, y1 = pcy + 0.5f * ph;
        x0 = fminf(fmaxf(x0, 0.f), IMGSZ);
        y0 = fminf(fmaxf(y0, 0.f), IMGSZ);
        x1 = fminf(fmaxf(x1, 0.f), IMGSZ);
        y1 = fminf(fmaxf(y1, 0.f), IMGSZ);
        bool valid = ((x1 - x0) >= MIN_SIZE) && ((y1 - y0) >= MIN_SIZE);

        g_tmpB[i] = make_float4(x0, y0, x1, y1);
        g_tmpS[i] = valid ? g_topScore[i] : -1.0f;
        sFlag[i] = valid ? 1 : 0;
    }
    __syncthreads();

    // inclusive scan over 2048
    int* src = sA; int* dst = sB;
    for (int e = t; e < 2048; e += 1024) sA[e] = sFlag[e];
    __syncthreads();
    for (int off = 1; off < 2048; off <<= 1) {
        for (int e = t; e < 2048; e += 1024)
            dst[e] = src[e] + ((e >= off) ? src[e - off] : 0);
        __syncthreads();
        int* tmp = src; src = dst; dst = tmp;
    }
    const int nvalid = src[2047];
    if (t == 0) g_nvalid = nvalid;
    for (int i = t; i < PRENMS; i += 1024) {
        int f = sFlag[i];
        int rank = src[i] - f;          // exclusive rank among valid
        int pos = f ? rank : (nvalid + (i - rank));   // stable partition
        g_B[pos] = g_tmpB[i];
        g_SC[pos] = g_tmpS[i];
    }
}

// ---------------- kernel 9: NMS suppression masks ----------------
__global__ __launch_bounds__(64) void k_nms() {
    const int cb = blockIdx.x, rb = blockIdx.y;
    __shared__ float4 cbx[64];
    const int t = threadIdx.x;
    const int j0 = cb * 64;
    if (j0 + t < PRENMS) cbx[t] = g_B[j0 + t];
    __syncthreads();
    const int i = rb * 64 + t;
    if (i >= PRENMS) return;
    const float4 bi = g_B[i];
    const float areai = (bi.z - bi.x) * (bi.w - bi.y);
    unsigned long long m = 0ULL;
    const int jmax = min(64, PRENMS - j0);
    for (int jj = 0; jj < jmax; ++jj) {
        int j = j0 + jj;
        if (j <= i) continue;
        float4 bj = cbx[jj];
        float xx1 = fmaxf(bi.x, bj.x), yy1 = fmaxf(bi.y, bj.y);
        float xx2 = fminf(bi.z, bj.z), yy2 = fminf(bi.w, bj.w);
        float ww = fmaxf(xx2 - xx1, 0.f), hh = fmaxf(yy2 - yy1, 0.f);
        float inter = ww * hh;
        float areaj = (bj.z - bj.x) * (bj.w - bj.y);
        float iou = inter / (areai + areaj - inter + 1e-9f);
        if (iou > NMS_TH) m |= (1ULL << jj);
    }
    g_mask[(size_t)i * 32 + cb] = m;
}

// ---------------- kernel 10: sequential NMS scan + compact output ----------------
__global__ __launch_bounds__(1024) void k_final(float* __restrict__ out, int out_size) {
    const int t = threadIdx.x;
    for (int i = t; i < out_size; i += 1024) out[i] = 0.f;
    __shared__ unsigned char keepS[2048];
    __shared__ int sA[2048], sB[2048];
    for (int i = t; i < 2048; i += 1024) keepS[i] = 0;
    __syncthreads();

    if (t < 32) {
        const int PF = 8;
        unsigned long long rem = 0ULL;
        unsigned long long buf[PF];
        #pragma unroll
        for (int k = 0; k < PF; ++k) buf[k] = g_mask[(size_t)k * 32 + t];
        const int nv = g_nvalid;
        for (int i = 0; i < PRENMS; ++i) {
            unsigned long long w = __shfl_sync(0xffffffffu, rem, i >> 6);
            bool kept = (i < nv) && !((w >> (i & 63)) & 1ULL);
            unsigned long long row = buf[i & (PF - 1)];
            if (i + PF < PRENMS) buf[i & (PF - 1)] = g_mask[(size_t)(i + PF) * 32 + t];
            if (kept) rem |= row;
            if (t == 0) keepS[i] = kept ? 1 : 0;
        }
    }
    __syncthreads();

    int* src = sA; int* dst = sB;
    for (int e = t; e < 2048; e += 1024) sA[e] = keepS[e];
    __syncthreads();
    for (int off = 1; off < 2048; off <<= 1) {
        for (int e = t; e < 2048; e += 1024)
            dst[e] = src[e] + ((e >= off) ? src[e - off] : 0);
        __syncthreads();
        int* tmp = src; src = dst; dst = tmp;
    }
    for (int i = t; i < PRENMS; i += 1024) {
        if (keepS[i]) {
            int rank = src[i] - 1;
            if (rank < RPN_TOPK) {
                float4 b = g_B[i];
                out[rank * 4 + 0] = b.x;
                out[rank * 4 + 1] = b.y;
                out[rank * 4 + 2] = b.z;
                out[rank * 4 + 3] = b.w;
                out[out_size - RPN_TOPK + rank] = g_SC[i];
            }
        }
    }
}

// ---------------- launch ----------------
extern "C" void kernel_launch(void* const* d_in, const int* in_sizes, int n_in,
                              void* d_out, int out_size) {
    const float* feat   = (const float*)d_in[1];
    const float* conv_w = (const float*)d_in[2];
    const float* conv_b = (const float*)d_in[3];
    const float* cls_w  = (const float*)d_in[4];
    const float* cls_b  = (const float*)d_in[5];
    const float* reg_w  = (const float*)d_in[6];
    const float* reg_b  = (const float*)d_in[7];
    float* out = (float*)d_out;

    k_init<<<1, 256>>>();
    k_transw<<<2304, 256>>>(conv_w);
    k_conv<<<dim3(25, 25, 2), 256>>>(feat, conv_b);
    k_head<<<(NPIX + 255) / 256, 256>>>(cls_w, cls_b, reg_w, reg_b);
    for (int pass = 0; pass < 3; ++pass) {
        k_hist<<<512, 256>>>(pass);
        k_select<<<1, 256>>>();
    }
    k_compact<<<512, 256>>>();
    k_sort<<<1, 1024>>>();
    k_prop<<<1, 1024>>>();
    k_nms<<<dim3(32, 32), 64>>>();
    k_final<<<1, 1024>>>(out, out_size);
}